// round 16
// baseline (speedup 1.0000x reference)
#include <cuda_runtime.h>

#define BB 64
#define NN 512
#define EPS 1e-10f

// Scratch (allocation-free rule: __device__ globals; zero-init at load,
// reset by the finalize block each run for graph replay)
__device__ float2   g_items[BB * NN];   // rel-sorted: {disc, exp(score)}
__device__ unsigned g_done[BB];         // per-row prep arrival counters
__device__ float    g_accum = 0.0f;
__device__ unsigned g_count = 0u;

// Single fused kernel. grid (16, 64), 256 threads, all 1024 blocks co-resident.
// Phase 1: block q ranks items [q*32, q*32+32) with 8 thr/item: vectorized
//          float4 score scan + SIMD byte scan for deterministic placement.
//          Every block redundantly computes row constants (balanced).
// Row barrier: fence + arrive + poll on g_done[row] (16 arrivals).
// Phase 2: bucket-segmented valid pairs (≈5 instr/pair), 16 j-chunks.
__global__ __launch_bounds__(256, 8)
void lr_fused(const float* __restrict__ scores,
              const float* __restrict__ relevance,
              float* __restrict__ out) {
    const int q   = blockIdx.x;      // 0..15
    const int row = blockIdx.y;
    const int t   = threadIdx.x;

    __shared__ float2   buf[NN];     // ph1 alias: float ss[512]; ph2: {d,E}
    __shared__ unsigned srelW[NN / 4]; // relevance packed as bytes
    __shared__ int      counts[5];
    __shared__ int      stS[6];      // segment starts {0, b4, b3, b2, b1, 512}
    __shared__ float    wred[8];

    float* ss = reinterpret_cast<float*>(buf);
    unsigned char* srel = reinterpret_cast<unsigned char*>(srelW);

    // ---------------- Phase 1: prep ----------------
    if (t < 5) counts[t] = 0;
    ss[t]       = scores[row * NN + t];
    ss[t + 256] = scores[row * NN + t + 256];
    int r0 = (int)relevance[row * NN + t];
    int r1 = (int)relevance[row * NN + t + 256];
    srel[t]       = (unsigned char)r0;
    srel[t + 256] = (unsigned char)r1;
    __syncthreads();

    // histogram via ballots (4 atomics per warp, lane 0)
    {
        int h1 = __popc(__ballot_sync(~0u, r0 == 1)) + __popc(__ballot_sync(~0u, r1 == 1));
        int h2 = __popc(__ballot_sync(~0u, r0 == 2)) + __popc(__ballot_sync(~0u, r1 == 2));
        int h3 = __popc(__ballot_sync(~0u, r0 == 3)) + __popc(__ballot_sync(~0u, r1 == 3));
        int h4 = __popc(__ballot_sync(~0u, r0 == 4)) + __popc(__ballot_sync(~0u, r1 == 4));
        if ((t & 31) == 0) {
            atomicAdd(&counts[1], h1); atomicAdd(&counts[2], h2);
            atomicAdd(&counts[3], h3); atomicAdd(&counts[4], h4);
        }
    }

    // ---- vectorized rank scan: 8 thr/item, vectors m = 8*mm+part ----
    const int   i    = q * 32 + (t >> 3);
    const int   part = t & 7;
    const float si   = ss[i];
    const int   Mb   = i >> 2;                     // boundary vector index
    const int   thrA = (Mb - part + 7) >> 3;       // #mm with 8mm+part < Mb
    const bool  ownB = ((Mb & 7) == part);
    const float4* ss4 = reinterpret_cast<const float4*>(ss);

    int rk = 0;
    #pragma unroll 4
    for (int mm = 0; mm < thrA; ++mm) {            // vectors fully below i
        float4 v = ss4[8 * mm + part];
        rk += (v.x >= si) + (v.y >= si) + (v.z >= si) + (v.w >= si);
    }
    if (ownB) {                                    // boundary vector
        float4 v = ss4[Mb];
        int e0 = i & 3;                            // self element
        rk += (0 < e0) ? (v.x >= si) : (v.x > si);
        rk += (1 < e0) ? (v.y >= si) : (v.y > si);
        rk += (2 < e0) ? (v.z >= si) : (v.z > si);
        rk += (3 < e0) ? (v.w >= si) : (v.w > si);
    }
    {
        const int thrB = (Mb - part + 8) >> 3;     // first mm with 8mm+part > Mb
        #pragma unroll 4
        for (int mm = thrB; mm < 16; ++mm) {       // vectors fully above i
            float4 v = ss4[8 * mm + part];
            rk += (v.x > si) + (v.y > si) + (v.z > si) + (v.w > si);
        }
    }

    // ---- SIMD byte scan for same-rel count (j < i, rel_j == rel_i) ----
    const int ri = (int)((srelW[Mb] >> (8 * (i & 3))) & 0xFFu);
    {
        const unsigned rrep = (unsigned)ri * 0x01010101u;
        const int nFull = thrA;                    // words below boundary word
        int same = 0;
        #pragma unroll 4
        for (int mm = 0; mm < nFull; ++mm) {
            unsigned x = srelW[8 * mm + part];
            same += __popc(__vcmpeq4(x, rrep) & 0x01010101u);
        }
        if (ownB) {                                // partial boundary word
            unsigned m = (i & 3) ? (0xFFFFFFFFu >> (32 - 8 * (i & 3))) : 0u;
            same += __popc(__vcmpeq4(srelW[Mb], rrep) & 0x01010101u & m);
        }
        rk |= same << 16;                          // pack; no cross-field carry
    }
    rk += __shfl_down_sync(0xffffffffu, rk, 4, 8);
    rk += __shfl_down_sync(0xffffffffu, rk, 2, 8);
    rk += __shfl_down_sync(0xffffffffu, rk, 1, 8);

    __syncthreads();                               // histogram complete
    const int c4 = counts[4], c3 = counts[3], c2 = counts[2], c1 = counts[1];
    const int b4 = c4, b3 = b4 + c3, b2 = b3 + c2, b1 = b2 + c1;

    if (part == 0) {
        int rkT   = rk & 0xffff;
        int sameT = rk >> 16;
        int base = (ri == 4) ? 0 : (ri == 3) ? b4 : (ri == 2) ? b3
                 : (ri == 1) ? b2 : b1;
        float d = __fdividef(1.0f, __log2f((float)(rkT + 3)));  // rank = rkT+1
        g_items[row * NN + base + sameT] = make_float2(d, __expf(si));
    }

    // row scale: redundant in EVERY block (balanced)
    float scale = 0.0f;                            // valid on t==0
    {
        float v = 0.0f;
        #pragma unroll
        for (int h = 0; h < 2; ++h) {
            int p = t + h * 256;
            float gl = p < b4 ? 15.f : p < b3 ? 7.f : p < b2 ? 3.f : p < b1 ? 1.f : 0.f;
            v += __fdividef(gl, __log2f((float)(p + 2)));
        }
        #pragma unroll
        for (int o = 16; o > 0; o >>= 1) v += __shfl_down_sync(0xffffffffu, v, o);
        if ((t & 31) == 0) wred[t >> 5] = v;
        if (t == 0) {
            stS[0] = 0; stS[1] = b4; stS[2] = b3;
            stS[3] = b2; stS[4] = b1; stS[5] = NN;
        }
        __syncthreads();                           // also orders g_items stores
        if (t == 0) {
            float idcg = fmaxf(wred[0] + wred[1] + wred[2] + wred[3] +
                               wred[4] + wred[5] + wred[6] + wred[7], EPS);
            int c0 = NN - b1;
            float sq = (float)c4 * c4 + (float)c3 * c3 + (float)c2 * c2 +
                       (float)c1 * c1 + (float)c0 * c0;
            float cntf = 0.5f * ((float)NN * NN - sq);
            scale = 0.6931471805599453f / (idcg * (cntf + EPS)) / (float)BB;
        }
    }

    // ---------------- Row barrier (16 arrivals) ----------------
    if (t == 0) {
        __threadfence();
        atomicAdd(&g_done[row], 1u);
        while (atomicAdd(&g_done[row], 0u) < 16u) {}
    }
    __syncthreads();

    // ---------------- Phase 2: bucket-segmented valid pairs ----------------
    reinterpret_cast<float4*>(buf)[t] =
        __ldcg(reinterpret_cast<const float4*>(g_items + row * NN) + t);
    __syncthreads();

    float acc = 0.0f;
    #pragma unroll
    for (int it = 0; it < 2; ++it) {
        const int p = it ? (NN - 1 - t) : t;
        int bk = (p >= stS[1]) + (p >= stS[2]) + (p >= stS[3]) + (p >= stS[4]);
        float gi = (float)((16 >> bk) - 1);
        int bkw = __shfl_sync(0xffffffffu, bk, it ? 31 : 0);   // warp-min bucket
        float2 me = buf[p];
        float di   = me.x;
        float Einv = __fdividef(1.0f, me.y);                   // exp(-s_i)
        int lo  = stS[bkw + 1];                                // bkw==4 -> 512
        int len = NN - lo;
        int j0 = lo + ((q * len) >> 4);                        // 16 chunks
        int j1 = lo + (((q + 1) * len) >> 4);

        for (int s = bkw + 1; s < 5; ++s) {                    // warp-uniform
            int a = max(j0, stS[s]);
            int b = min(j1, stS[s + 1]);
            float C = fmaxf(gi - (float)((16 >> s) - 1), 0.0f);
            float partsum = 0.0f;
            #pragma unroll 4
            for (int j = a; j < b; ++j) {                      // broadcast LDS
                float2 v = buf[j];
                float dd = di - v.x;
                float lg = __log2f(fmaf(Einv, v.y, 1.0f));
                partsum = fmaf(fabsf(dd), lg, partsum);
            }
            acc = fmaf(C, partsum, acc);
        }
    }

    // block reduce (8 warps)
    #pragma unroll
    for (int o = 16; o > 0; o >>= 1) acc += __shfl_down_sync(0xffffffffu, acc, o);
    if ((t & 31) == 0) wred[t >> 5] = acc;
    __syncthreads();
    if (t == 0) {
        float bs = wred[0] + wred[1] + wred[2] + wred[3] +
                   wred[4] + wred[5] + wred[6] + wred[7];
        atomicAdd(&g_accum, bs * scale);
        __threadfence();
        unsigned n = atomicAdd(&g_count, 1u);
        if (n == 16u * BB - 1u) {            // last block finalizes + resets
            out[0] = atomicAdd(&g_accum, 0.0f);
            g_accum = 0.0f;
            g_count = 0u;
            #pragma unroll 4
            for (int k = 0; k < BB; ++k) g_done[k] = 0u;
        }
    }
}

extern "C" void kernel_launch(void* const* d_in, const int* in_sizes, int n_in,
                              void* d_out, int out_size) {
    const float* scores    = (const float*)d_in[0];
    const float* relevance = (const float*)d_in[1];
    float* out = (float*)d_out;

    lr_fused<<<dim3(16, BB), 256>>>(scores, relevance, out);
}